// round 16
// baseline (speedup 1.0000x reference)
#include <cuda_runtime.h>
#include <cuda_fp16.h>
#include <cstdint>
#include <math.h>

#define BATCH 2
#define SEQ   4096
#define HID   1024
#define DIM   64
#define CHUNK 64
#define NCHUNK (SEQ/CHUNK)
#define NROWS (BATCH*SEQ)
#define GAMMA_F 0.96875f
#define NTOT 192
#define LG2G (-0.045803689613124785f) // log2(0.96875)
#define WSCALE 1024.0f
#define INV_WSCALE (1.0f/1024.0f)

// ---------------- scratch (static device globals; no runtime alloc) ----------
__device__ __half g_Wh[NTOT*HID];          // W^T * 1024: [n][k], fp16 hi
__device__ __half g_Wl[NTOT*HID];          // fp16 lo residual
__device__ float2 g_qtab[32*SEQ];          // (cos*sc, sin*sc) [pr][pos]
__device__ float2 g_ktab[32*SEQ];          // (cos/sc, sin/sc)
__device__ float g_Q[NROWS*DIM];
__device__ float g_K[NROWS*DIM];
__device__ float g_V[NROWS*DIM];
__device__ float g_G[BATCH*NCHUNK*DIM*DIM];
__device__ float g_A[BATCH*NCHUNK*DIM*DIM];

// ---------------- warp-level fp16 MMA + ldmatrix (sm_75+/80+) ----------------
__device__ __forceinline__ void mma_fp16(float* c, const uint32_t* a, const uint32_t* b) {
    asm volatile(
        "mma.sync.aligned.m16n8k16.row.col.f32.f16.f16.f32 "
        "{%0,%1,%2,%3}, {%4,%5,%6,%7}, {%8,%9}, {%0,%1,%2,%3};"
        : "+f"(c[0]), "+f"(c[1]), "+f"(c[2]), "+f"(c[3])
        : "r"(a[0]), "r"(a[1]), "r"(a[2]), "r"(a[3]), "r"(b[0]), "r"(b[1]));
}
__device__ __forceinline__ void ldsm_x4(uint32_t* r, uint32_t addr) {
    asm volatile("ldmatrix.sync.aligned.m8n8.x4.shared.b16 {%0,%1,%2,%3}, [%4];"
        : "=r"(r[0]), "=r"(r[1]), "=r"(r[2]), "=r"(r[3]) : "r"(addr));
}
__device__ __forceinline__ uint32_t pack_h2(__half lo, __half hi) {
    return (uint32_t)__half_as_ushort(lo) | ((uint32_t)__half_as_ushort(hi) << 16);
}

// ================= P0: merged prep (xPos tables + W transpose/split) =========
__global__ void prep_kernel(const float* __restrict__ WQ,
                            const float* __restrict__ WK,
                            const float* __restrict__ WV) {
    int bid = blockIdx.x;
    int t   = threadIdx.x;
    if (bid < 512) {
        int id  = bid * 256 + t;            // 0 .. 32*4096-1
        int pr  = id >> 12;
        int pos = id & (SEQ - 1);
        float fp = (float)pos;
        float inv_freq = 1.0f / powf(10000.0f, (float)pr * (1.0f / 32.0f));
        float sv = (2.0f * pr + 0.4f * 64.0f) * (1.0f / (1.4f * 64.0f));
        float sc = powf(sv, fp * (1.0f / 512.0f));
        float sn, cs;
        sincosf(fp * inv_freq, &sn, &cs);
        float2 q, k;
        q.x = cs * sc;  q.y = sn * sc;
        float rs = 1.0f / sc;
        k.x = cs * rs;  k.y = sn * rs;
        g_qtab[pr * SEQ + pos] = q;
        g_ktab[pr * SEQ + pos] = k;
    } else {
        int n = bid - 512;                  // 0..191
        const float* W = (n < 64) ? WQ : ((n < 128) ? WK : WV);
        int cc = n & 63;
        for (int k = t; k < HID; k += 256) {
            float w = W[k * DIM + cc] * WSCALE;   // exact scale (pow2)
            __half h = __float2half(w);
            g_Wh[n * HID + k] = h;
            g_Wl[n * HID + k] = __float2half(w - __half2float(h));
        }
    }
}

// ===== K1: HMMA fp16 GEMM + xPos epilogue + FUSED chunk-KV (G) ===============
// 2-term (hi+lo) for Q/K columns; hi-only for V columns (error budget).
#define PA2 72   // smem pitch in fp16 units (144B = 36 banks): LDSM conflict-free
#define OFF_A  0
#define OFF_BH (64 * PA2 * 2)                       // 9216
#define OFF_BL (OFF_BH + NTOT * PA2 * 2)            // 36864
#define GEMM_SMEM (OFF_BL + NTOT * PA2 * 2)         // 64512
#define PKF 68   // K/V smem pitch (floats) for the fused G phase

__global__ __launch_bounds__(256) void gemm_kernel(const float* __restrict__ X) {
    extern __shared__ char smp[];
    __half* Ah = (__half*)(smp + OFF_A);
    __half* Bh = (__half*)(smp + OFF_BH);
    __half* Bl = (__half*)(smp + OFF_BL);
    __shared__ float wsm[CHUNK];

    const int t    = threadIdx.x;
    const int wid  = t >> 5, lane = t & 31;
    const int g    = lane >> 2, tig = lane & 3;
    const int wm   = wid >> 2, wn = wid & 3;     // warp grid 2 x 4
    const int r0   = blockIdx.x * 64;

    if (t < CHUNK) wsm[t] = powf(GAMMA_F, (float)(CHUNK - t));

    const uint32_t uAh = (uint32_t)__cvta_generic_to_shared(Ah);
    const uint32_t uBh = (uint32_t)__cvta_generic_to_shared(Bh);
    const uint32_t uBl = (uint32_t)__cvta_generic_to_shared(Bl);
    // per-lane ldmatrix element offsets (in fp16 units)
    const int aoff = (wm * 32 + (lane & 15)) * PA2 + ((lane >> 4) << 3);
    const int boff = (wn * 48 + ((lane >> 4) << 3) + (lane & 7)) * PA2 + (((lane >> 3) & 1) << 3);
    // lo-term column limit: warp wn covers cols [wn*48, wn*48+48); V starts at 128.
    // nt < ntLo gets the Wl residual MMA; V columns are hi-only.
    const int ntLo = (wn < 2) ? 6 : ((wn == 2) ? 4 : 0);

    float C[2][6][4];
    #pragma unroll
    for (int mt = 0; mt < 2; mt++)
        #pragma unroll
        for (int nt = 0; nt < 6; nt++)
            #pragma unroll
            for (int i = 0; i < 4; i++) C[mt][nt][i] = 0.f;

    // prefetch registers: A 4 float4, B 6+6 uint4
    float4 pxa[4];
    uint4  pbh[6], pbl[6];

    #pragma unroll
    for (int j = 0; j < 4; j++) {
        int id = t + 256 * j;
        pxa[j] = *(const float4*)(X + (size_t)(r0 + (id >> 4)) * HID + (id & 15) * 4);
    }
    #pragma unroll
    for (int j = 0; j < 6; j++) {
        int id = t + 256 * j;
        int n = id >> 3, k8 = (id & 7) * 8;
        pbh[j] = *(const uint4*)(g_Wh + (size_t)n * HID + k8);
        pbl[j] = *(const uint4*)(g_Wl + (size_t)n * HID + k8);
    }

    for (int c = 0; c < 16; c++) {
        __syncthreads();           // previous chunk's compute done
        // ---- store A (fp32 -> fp16)
        #pragma unroll
        for (int j = 0; j < 4; j++) {
            int id = t + 256 * j;
            int row = id >> 4, col4 = (id & 15) * 4;
            float4 v = pxa[j];
            *(uint2*)(Ah + row * PA2 + col4) =
                make_uint2(pack_h2(__float2half(v.x), __float2half(v.y)),
                           pack_h2(__float2half(v.z), __float2half(v.w)));
        }
        #pragma unroll
        for (int j = 0; j < 6; j++) {
            int id = t + 256 * j;
            int n = id >> 3, k8 = (id & 7) * 8;
            *(uint4*)(Bh + n * PA2 + k8) = pbh[j];
            *(uint4*)(Bl + n * PA2 + k8) = pbl[j];
        }
        __syncthreads();
        // ---- prefetch chunk c+1 (overlaps compute below)
        if (c < 15) {
            int kt = (c + 1) * 64;
            #pragma unroll
            for (int j = 0; j < 4; j++) {
                int id = t + 256 * j;
                pxa[j] = *(const float4*)(X + (size_t)(r0 + (id >> 4)) * HID + kt + (id & 15) * 4);
            }
            #pragma unroll
            for (int j = 0; j < 6; j++) {
                int id = t + 256 * j;
                int n = id >> 3, k8 = (id & 7) * 8;
                pbh[j] = *(const uint4*)(g_Wh + (size_t)n * HID + kt + k8);
                pbl[j] = *(const uint4*)(g_Wl + (size_t)n * HID + kt + k8);
            }
        }
        // ---- compute: 4 k16 steps, fragments via ldmatrix
        #pragma unroll
        for (int ks = 0; ks < 4; ks++) {
            const int ko = ks * 16;
            uint32_t fah[2][4];
            #pragma unroll
            for (int mt = 0; mt < 2; mt++)
                ldsm_x4(fah[mt], uAh + (uint32_t)(aoff + mt * 16 * PA2 + ko) * 2);
            uint32_t fbh[6][2], fbl[6][2];
            #pragma unroll
            for (int p3 = 0; p3 < 3; p3++) {
                uint32_t eo = (uint32_t)(boff + p3 * 16 * PA2 + ko) * 2;
                uint32_t tmp[4];
                ldsm_x4(tmp, uBh + eo);
                fbh[2*p3][0] = tmp[0]; fbh[2*p3][1] = tmp[1];
                fbh[2*p3+1][0] = tmp[2]; fbh[2*p3+1][1] = tmp[3];
                if (2 * p3 < ntLo) {               // lo fragments only for Q/K cols
                    ldsm_x4(tmp, uBl + eo);
                    fbl[2*p3][0] = tmp[0]; fbl[2*p3][1] = tmp[1];
                    fbl[2*p3+1][0] = tmp[2]; fbl[2*p3+1][1] = tmp[3];
                }
            }
            #pragma unroll
            for (int mt = 0; mt < 2; mt++)
                #pragma unroll
                for (int nt = 0; nt < 6; nt++) {
                    mma_fp16(C[mt][nt], fah[mt], fbh[nt]);
                    if (nt < ntLo)
                        mma_fp16(C[mt][nt], fah[mt], fbl[nt]);
                }
        }
    }

    // -------- epilogue: undo WSCALE, xPos tables, write g_Q/g_K/g_V,
    //          and stage K/V into smem for the fused G phase ------------------
    __syncthreads();               // all LDSM reads done before smem reuse
    float* Ksm = (float*)smp;                  // [64][PKF]
    float* Vsm = (float*)smp + 64 * PKF;       // [64][PKF]

    #pragma unroll
    for (int mt = 0; mt < 2; mt++) {
        int rla = wm * 32 + mt * 16 + g;       // local row in chunk
        int rlb = rla + 8;
        int ra = r0 + rla, rb = r0 + rlb;
        int pa_ = ra & (SEQ - 1), pb_ = rb & (SEQ - 1);
        #pragma unroll
        for (int nt = 0; nt < 6; nt++) {
            int gc = wn * 48 + nt * 8 + tig * 2;
            float v0 = C[mt][nt][0] * INV_WSCALE, v1 = C[mt][nt][1] * INV_WSCALE;
            float v2 = C[mt][nt][2] * INV_WSCALE, v3 = C[mt][nt][3] * INV_WSCALE;
            if (gc >= 128) {               // V passthrough
                int lc = gc - 128;
                *(float2*)(g_V + (size_t)ra * DIM + lc) = make_float2(v0, v1);
                *(float2*)(g_V + (size_t)rb * DIM + lc) = make_float2(v2, v3);
                *(float2*)(Vsm + rla * PKF + lc) = make_float2(v0, v1);
                *(float2*)(Vsm + rlb * PKF + lc) = make_float2(v2, v3);
            } else {                       // Q / K rotation
                const float2* tab = (gc < 64) ? g_qtab : g_ktab;
                int pr = (gc & 63) >> 1;
                float2 ta = tab[pr * SEQ + pa_];
                float2 tb = tab[pr * SEQ + pb_];
                int lc = gc & 63;
                float2 oa = make_float2(v0 * ta.x - v1 * ta.y, v1 * ta.x + v0 * ta.y);
                float2 ob = make_float2(v2 * tb.x - v3 * tb.y, v3 * tb.x + v2 * tb.y);
                if (gc < 64) {
                    *(float2*)(g_Q + (size_t)ra * DIM + lc) = oa;
                    *(float2*)(g_Q + (size_t)rb * DIM + lc) = ob;
                } else {
                    *(float2*)(g_K + (size_t)ra * DIM + lc) = oa;
                    *(float2*)(g_K + (size_t)rb * DIM + lc) = ob;
                    *(float2*)(Ksm + rla * PKF + lc) = oa;
                    *(float2*)(Ksm + rlb * PKF + lc) = ob;
                }
            }
        }
    }
    __syncthreads();

    // -------- fused G: G[a][d] = sum_j gamma^(64-j) K[j][a] V[j][d] ----------
    {
        const int a0 = (t >> 4) * 4;
        const int d0 = (t & 15) * 4;
        float acc[4][4];
        #pragma unroll
        for (int p = 0; p < 4; p++)
            #pragma unroll
            for (int q = 0; q < 4; q++) acc[p][q] = 0.f;

        for (int j = 0; j < CHUNK; j++) {
            float wj = wsm[j];
            float4 kq = *(const float4*)(Ksm + j * PKF + a0);
            float4 vq = *(const float4*)(Vsm + j * PKF + d0);
            float ka[4] = { kq.x * wj, kq.y * wj, kq.z * wj, kq.w * wj };
            float vd[4] = { vq.x, vq.y, vq.z, vq.w };
            #pragma unroll
            for (int p = 0; p < 4; p++)
                #pragma unroll
                for (int q = 0; q < 4; q++)
                    acc[p][q] = fmaf(ka[p], vd[q], acc[p][q]);
        }

        int gbase = blockIdx.x * DIM * DIM;    // blockIdx == global chunk index
        #pragma unroll
        for (int p = 0; p < 4; p++)
            *(float4*)(g_G + gbase + (a0 + p) * DIM + d0) =
                make_float4(acc[p][0], acc[p][1], acc[p][2], acc[p][3]);
    }
}

// ==== K3: elementwise scan, MLP=32 x 2 groups (fits registers, no spill) =====
__global__ __launch_bounds__(128) void scan_kernel() {
    int e = blockIdx.x * 128 + threadIdx.x;          // 0..8191
    int b  = e >> 12;
    int ed = e & (DIM * DIM - 1);
    const float g64 = powf(GAMMA_F, 64.0f);
    int base = b * NCHUNK * DIM * DIM + ed;
    const float* Gp = g_G + base;
    float*       Ap = g_A + base;
    float acc = 0.f;
    #pragma unroll
    for (int grp = 0; grp < 2; grp++) {
        float buf[32];
        #pragma unroll
        for (int u = 0; u < 32; u++)                 // 32 independent LDGs
            buf[u] = Gp[(grp * 32 + u) * (DIM * DIM)];
        #pragma unroll
        for (int u = 0; u < 32; u++) {
            Ap[(grp * 32 + u) * (DIM * DIM)] = acc;  // state BEFORE chunk
            acc = acc * g64 + buf[u];
        }
    }
}

// == K4: out = (Q K^T .* decay) V + diag(g^i)(Q A_c)
//    512 threads, 2x2 micro-tile, 2 blocks/chunk + CAUSAL SKIP for half 0.
#define PQ 34   // Qt/St pitch (floats): float2-aligned, conflict-free
#define PK 68   // Kt/Vt pitch (floats): float2/float4-aligned, conflict-free

__global__ __launch_bounds__(512) void out_kernel(float* __restrict__ out) {
    __shared__ float Qt[64 * PQ];   // [a][i]  a=0..63, i=0..31
    __shared__ float Kt[64 * PK];   // [a][j], reused as V [j][d] in phase 2
    __shared__ float St[64 * PQ];   // [j][i]

    const int t    = threadIdx.x;
    const int idx  = blockIdx.x;
    const int half = idx & 1;
    const int c    = (idx >> 1) & (NCHUNK - 1);
    const int b    = idx >> 7;
    const int base  = (b * SEQ + c * CHUNK) * DIM;
    const int rbase = base + half * 32 * DIM;
    const int jmax  = half ? CHUNK : 32;     // half 0: rows 0..31 -> j<32 only
    const int qk    = jmax >> 3;             // K/V load groups (rows j < jmax)

    // Qt[a][i] = Q[rbase + i*64 + a]; Kt[a][j] = K[base + j*64 + a] (j < jmax)
    #pragma unroll
    for (int q = 0; q < 4; q++) {
        int f = t + 512 * q;                 // i = f>>6, a = f&63
        Qt[(f & 63) * PQ + (f >> 6)] = g_Q[rbase + f];
    }
    for (int q = 0; q < qk; q++) {
        int f = t + 512 * q;                 // j = f>>6, a = f&63
        Kt[(f & 63) * PK + (f >> 6)] = g_K[base + f];
    }
    __syncthreads();

    const int ti = t >> 5, tj = t & 31;      // 16 x 32 thread grid
    const int i0 = ti * 2, j0 = tj * 2;

    // ---- phase 1: S = (Q K^T) .* gamma^(gi-j) causal mask (j < jmax)
    if (j0 < jmax) {
        float s[2][2];
        s[0][0] = s[0][1] = s[1][0] = s[1][1] = 0.f;

        for (int a = 0; a < DIM; a++) {
            float2 qa = *(const float2*)(Qt + a * PQ + i0);
            float2 kb = *(const float2*)(Kt + a * PK + j0);
            s[0][0] = fmaf(qa.x, kb.x, s[0][0]);
            s[0][1] = fmaf(qa.x, kb.y, s[0][1]);
            s[1][0] = fmaf(qa.y, kb.x, s[1][0]);
            s[1][1] = fmaf(qa.y, kb.y, s[1][1]);
        }
        #pragma unroll
        for (int p = 0; p < 2; p++) {
            int gi = half * 32 + i0 + p;
            #pragma unroll
            for (int q = 0; q < 2; q++) {
                int j = j0 + q;
                float v = (gi >= j) ? s[p][q] * exp2f(LG2G * (float)(gi - j)) : 0.f;
                St[j * PQ + (i0 + p)] = v;
            }
        }
    }
    __syncthreads();

    // overwrite Kt with V in [j][d] layout (j < jmax)
    for (int q = 0; q < qk; q++) {
        int f = t + 512 * q;                 // j = f>>6, d = f&63
        Kt[(f >> 6) * PK + (f & 63)] = g_V[base + f];
    }
    __syncthreads();

    // ---- phase 2: out = S V + diag * (Q A)
    const int d0 = tj * 2;
    float o[2][2];
    o[0][0] = o[0][1] = o[1][0] = o[1][1] = 0.f;

    for (int j = 0; j < jmax; j++) {
        float2 sp = *(const float2*)(St + j * PQ + i0);
        float2 vv = *(const float2*)(Kt + j * PK + d0);
        o[0][0] = fmaf(sp.x, vv.x, o[0][0]);
        o[0][1] = fmaf(sp.x, vv.y, o[0][1]);
        o[1][0] = fmaf(sp.y, vv.x, o[1][0]);
        o[1][1] = fmaf(sp.y, vv.y, o[1][1]);
    }

    const float* A = g_A + (b * NCHUNK + c) * DIM * DIM;
    float oa[2][2];
    oa[0][0] = oa[0][1] = oa[1][0] = oa[1][1] = 0.f;

    #pragma unroll 4
    for (int a = 0; a < DIM; a++) {
        float2 av = *(const float2*)(A + a * DIM + d0);
        float2 qa = *(const float2*)(Qt + a * PQ + i0);
        oa[0][0] = fmaf(qa.x, av.x, oa[0][0]);
        oa[0][1] = fmaf(qa.x, av.y, oa[0][1]);
        oa[1][0] = fmaf(qa.y, av.x, oa[1][0]);
        oa[1][1] = fmaf(qa.y, av.y, oa[1][1]);
    }

    #pragma unroll
    for (int p = 0; p < 2; p++) {
        int gi = half * 32 + i0 + p;
        float dec = exp2f(LG2G * (float)gi);
        float2 res;
        res.x = o[p][0] + dec * oa[p][0];
        res.y = o[p][1] + dec * oa[p][1];
        *(float2*)(out + rbase + (i0 + p) * 64 + d0) = res;
    }
}

// ============================== launch ======================================
extern "C" void kernel_launch(void* const* d_in, const int* in_sizes, int n_in,
                              void* d_out, int out_size)
{
    const float* X  = (const float*)d_in[0];
    const float* WQ = (const float*)d_in[1];
    const float* WK = (const float*)d_in[2];
    const float* WV = (const float*)d_in[3];
    float* out = (float*)d_out;

    cudaFuncSetAttribute(gemm_kernel,
                         cudaFuncAttributeMaxDynamicSharedMemorySize, GEMM_SMEM);

    prep_kernel<<<512 + NTOT, 256>>>(WQ, WK, WV);
    gemm_kernel<<<NROWS / 64, 256, GEMM_SMEM>>>(X);
    scan_kernel<<<(BATCH * DIM * DIM) / 128, 128>>>();
    out_kernel<<<BATCH * NCHUNK * 2, 512>>>(out);
}

// round 17
// speedup vs baseline: 1.5600x; 1.5600x over previous
#include <cuda_runtime.h>
#include <cuda_fp16.h>
#include <cstdint>
#include <math.h>

#define BATCH 2
#define SEQ   4096
#define HID   1024
#define DIM   64
#define CHUNK 64
#define NCHUNK (SEQ/CHUNK)
#define NROWS (BATCH*SEQ)
#define GAMMA_F 0.96875f
#define NTOT 192
#define LG2G (-0.045803689613124785f) // log2(0.96875)
#define WSCALE 1024.0f
#define INV_WSCALE (1.0f/1024.0f)

// ---------------- scratch (static device globals; no runtime alloc) ----------
__device__ __half g_Wh[NTOT*HID];          // W^T * 1024: [n][k], fp16 hi
__device__ __half g_Wl[NTOT*HID];          // fp16 lo residual
__device__ float2 g_qtab[32*SEQ];          // (cos*sc, sin*sc) [pr][pos]
__device__ float2 g_ktab[32*SEQ];          // (cos/sc, sin/sc)
__device__ float g_Q[NROWS*DIM];
__device__ float g_K[NROWS*DIM];
__device__ float g_V[NROWS*DIM];
__device__ float g_G[BATCH*NCHUNK*DIM*DIM];
__device__ float g_A[BATCH*NCHUNK*DIM*DIM];

// ---------------- warp-level fp16 MMA + ldmatrix (sm_75+/80+) ----------------
__device__ __forceinline__ void mma_fp16(float* c, const uint32_t* a, const uint32_t* b) {
    asm volatile(
        "mma.sync.aligned.m16n8k16.row.col.f32.f16.f16.f32 "
        "{%0,%1,%2,%3}, {%4,%5,%6,%7}, {%8,%9}, {%0,%1,%2,%3};"
        : "+f"(c[0]), "+f"(c[1]), "+f"(c[2]), "+f"(c[3])
        : "r"(a[0]), "r"(a[1]), "r"(a[2]), "r"(a[3]), "r"(b[0]), "r"(b[1]));
}
__device__ __forceinline__ void ldsm_x4(uint32_t* r, uint32_t addr) {
    asm volatile("ldmatrix.sync.aligned.m8n8.x4.shared.b16 {%0,%1,%2,%3}, [%4];"
        : "=r"(r[0]), "=r"(r[1]), "=r"(r[2]), "=r"(r[3]) : "r"(addr));
}
__device__ __forceinline__ uint32_t pack_h2(__half lo, __half hi) {
    return (uint32_t)__half_as_ushort(lo) | ((uint32_t)__half_as_ushort(hi) << 16);
}

// ================= P0: merged prep (xPos tables + W transpose/split) =========
__global__ void prep_kernel(const float* __restrict__ WQ,
                            const float* __restrict__ WK,
                            const float* __restrict__ WV) {
    int bid = blockIdx.x;
    int t   = threadIdx.x;
    if (bid < 512) {
        int id  = bid * 256 + t;            // 0 .. 32*4096-1
        int pr  = id >> 12;
        int pos = id & (SEQ - 1);
        float fp = (float)pos;
        float inv_freq = 1.0f / powf(10000.0f, (float)pr * (1.0f / 32.0f));
        float sv = (2.0f * pr + 0.4f * 64.0f) * (1.0f / (1.4f * 64.0f));
        float sc = powf(sv, fp * (1.0f / 512.0f));
        float sn, cs;
        sincosf(fp * inv_freq, &sn, &cs);
        float2 q, k;
        q.x = cs * sc;  q.y = sn * sc;
        float rs = 1.0f / sc;
        k.x = cs * rs;  k.y = sn * rs;
        g_qtab[pr * SEQ + pos] = q;
        g_ktab[pr * SEQ + pos] = k;
    } else {
        int n = bid - 512;                  // 0..191
        const float* W = (n < 64) ? WQ : ((n < 128) ? WK : WV);
        int cc = n & 63;
        for (int k = t; k < HID; k += 256) {
            float w = W[k * DIM + cc] * WSCALE;   // exact scale (pow2)
            __half h = __float2half(w);
            g_Wh[n * HID + k] = h;
            g_Wl[n * HID + k] = __float2half(w - __half2float(h));
        }
    }
}

// ===== K1: HMMA fp16 2-term GEMM + xPos epilogue + FUSED chunk-KV (G) ========
// D[8192 x 192] = X @ [WQ|WK|WV]*1024; per CTA M=64 = one retention chunk.
#define PA2 72   // smem pitch in fp16 units (144B = 36 banks): LDSM conflict-free
#define OFF_A  0
#define OFF_BH (64 * PA2 * 2)                       // 9216
#define OFF_BL (OFF_BH + NTOT * PA2 * 2)            // 36864
#define GEMM_SMEM (OFF_BL + NTOT * PA2 * 2)         // 64512
#define PKF 68   // K/V smem pitch (floats) for the fused G phase

__global__ __launch_bounds__(256) void gemm_kernel(const float* __restrict__ X) {
    extern __shared__ char smp[];
    __half* Ah = (__half*)(smp + OFF_A);
    __half* Bh = (__half*)(smp + OFF_BH);
    __half* Bl = (__half*)(smp + OFF_BL);
    __shared__ float wsm[CHUNK];

    const int t    = threadIdx.x;
    const int wid  = t >> 5, lane = t & 31;
    const int g    = lane >> 2, tig = lane & 3;
    const int wm   = wid >> 2, wn = wid & 3;     // warp grid 2 x 4
    const int r0   = blockIdx.x * 64;

    if (t < CHUNK) wsm[t] = powf(GAMMA_F, (float)(CHUNK - t));

    const uint32_t uAh = (uint32_t)__cvta_generic_to_shared(Ah);
    const uint32_t uBh = (uint32_t)__cvta_generic_to_shared(Bh);
    const uint32_t uBl = (uint32_t)__cvta_generic_to_shared(Bl);
    // per-lane ldmatrix element offsets (in fp16 units)
    const int aoff = (wm * 32 + (lane & 15)) * PA2 + ((lane >> 4) << 3);
    const int boff = (wn * 48 + ((lane >> 4) << 3) + (lane & 7)) * PA2 + (((lane >> 3) & 1) << 3);

    float C[2][6][4];
    #pragma unroll
    for (int mt = 0; mt < 2; mt++)
        #pragma unroll
        for (int nt = 0; nt < 6; nt++)
            #pragma unroll
            for (int i = 0; i < 4; i++) C[mt][nt][i] = 0.f;

    // prefetch registers: A 4 float4, B 6+6 uint4
    float4 pxa[4];
    uint4  pbh[6], pbl[6];

    #pragma unroll
    for (int j = 0; j < 4; j++) {
        int id = t + 256 * j;
        pxa[j] = *(const float4*)(X + (size_t)(r0 + (id >> 4)) * HID + (id & 15) * 4);
    }
    #pragma unroll
    for (int j = 0; j < 6; j++) {
        int id = t + 256 * j;
        int n = id >> 3, k8 = (id & 7) * 8;
        pbh[j] = *(const uint4*)(g_Wh + (size_t)n * HID + k8);
        pbl[j] = *(const uint4*)(g_Wl + (size_t)n * HID + k8);
    }

    for (int c = 0; c < 16; c++) {
        __syncthreads();           // previous chunk's compute done
        // ---- store A (fp32 -> fp16)
        #pragma unroll
        for (int j = 0; j < 4; j++) {
            int id = t + 256 * j;
            int row = id >> 4, col4 = (id & 15) * 4;
            float4 v = pxa[j];
            *(uint2*)(Ah + row * PA2 + col4) =
                make_uint2(pack_h2(__float2half(v.x), __float2half(v.y)),
                           pack_h2(__float2half(v.z), __float2half(v.w)));
        }
        #pragma unroll
        for (int j = 0; j < 6; j++) {
            int id = t + 256 * j;
            int n = id >> 3, k8 = (id & 7) * 8;
            *(uint4*)(Bh + n * PA2 + k8) = pbh[j];
            *(uint4*)(Bl + n * PA2 + k8) = pbl[j];
        }
        __syncthreads();
        // ---- prefetch chunk c+1 (overlaps compute below)
        if (c < 15) {
            int kt = (c + 1) * 64;
            #pragma unroll
            for (int j = 0; j < 4; j++) {
                int id = t + 256 * j;
                pxa[j] = *(const float4*)(X + (size_t)(r0 + (id >> 4)) * HID + kt + (id & 15) * 4);
            }
            #pragma unroll
            for (int j = 0; j < 6; j++) {
                int id = t + 256 * j;
                int n = id >> 3, k8 = (id & 7) * 8;
                pbh[j] = *(const uint4*)(g_Wh + (size_t)n * HID + kt + k8);
                pbl[j] = *(const uint4*)(g_Wl + (size_t)n * HID + kt + k8);
            }
        }
        // ---- compute: 4 k16 steps, fragments via ldmatrix
        #pragma unroll
        for (int ks = 0; ks < 4; ks++) {
            const int ko = ks * 16;
            uint32_t fah[2][4];
            #pragma unroll
            for (int mt = 0; mt < 2; mt++)
                ldsm_x4(fah[mt], uAh + (uint32_t)(aoff + mt * 16 * PA2 + ko) * 2);
            uint32_t fbh[6][2], fbl[6][2];
            #pragma unroll
            for (int p3 = 0; p3 < 3; p3++) {
                uint32_t eo = (uint32_t)(boff + p3 * 16 * PA2 + ko) * 2;
                uint32_t tmp[4];
                ldsm_x4(tmp, uBh + eo);
                fbh[2*p3][0] = tmp[0]; fbh[2*p3][1] = tmp[1];
                fbh[2*p3+1][0] = tmp[2]; fbh[2*p3+1][1] = tmp[3];
                ldsm_x4(tmp, uBl + eo);
                fbl[2*p3][0] = tmp[0]; fbl[2*p3][1] = tmp[1];
                fbl[2*p3+1][0] = tmp[2]; fbl[2*p3+1][1] = tmp[3];
            }
            #pragma unroll
            for (int mt = 0; mt < 2; mt++)
                #pragma unroll
                for (int nt = 0; nt < 6; nt++) {
                    mma_fp16(C[mt][nt], fah[mt], fbh[nt]);
                    mma_fp16(C[mt][nt], fah[mt], fbl[nt]);
                }
        }
    }

    // -------- epilogue: undo WSCALE, xPos tables, write g_Q/g_K/g_V,
    //          and stage K/V into smem for the fused G phase ------------------
    __syncthreads();               // all LDSM reads done before smem reuse
    float* Ksm = (float*)smp;                  // [64][PKF]
    float* Vsm = (float*)smp + 64 * PKF;       // [64][PKF]

    #pragma unroll
    for (int mt = 0; mt < 2; mt++) {
        int rla = wm * 32 + mt * 16 + g;       // local row in chunk
        int rlb = rla + 8;
        int ra = r0 + rla, rb = r0 + rlb;
        int pa_ = ra & (SEQ - 1), pb_ = rb & (SEQ - 1);
        #pragma unroll
        for (int nt = 0; nt < 6; nt++) {
            int gc = wn * 48 + nt * 8 + tig * 2;
            float v0 = C[mt][nt][0] * INV_WSCALE, v1 = C[mt][nt][1] * INV_WSCALE;
            float v2 = C[mt][nt][2] * INV_WSCALE, v3 = C[mt][nt][3] * INV_WSCALE;
            if (gc >= 128) {               // V passthrough
                int lc = gc - 128;
                *(float2*)(g_V + (size_t)ra * DIM + lc) = make_float2(v0, v1);
                *(float2*)(g_V + (size_t)rb * DIM + lc) = make_float2(v2, v3);
                *(float2*)(Vsm + rla * PKF + lc) = make_float2(v0, v1);
                *(float2*)(Vsm + rlb * PKF + lc) = make_float2(v2, v3);
            } else {                       // Q / K rotation
                const float2* tab = (gc < 64) ? g_qtab : g_ktab;
                int pr = (gc & 63) >> 1;
                float2 ta = tab[pr * SEQ + pa_];
                float2 tb = tab[pr * SEQ + pb_];
                int lc = gc & 63;
                float2 oa = make_float2(v0 * ta.x - v1 * ta.y, v1 * ta.x + v0 * ta.y);
                float2 ob = make_float2(v2 * tb.x - v3 * tb.y, v3 * tb.x + v2 * tb.y);
                if (gc < 64) {
                    *(float2*)(g_Q + (size_t)ra * DIM + lc) = oa;
                    *(float2*)(g_Q + (size_t)rb * DIM + lc) = ob;
                } else {
                    *(float2*)(g_K + (size_t)ra * DIM + lc) = oa;
                    *(float2*)(g_K + (size_t)rb * DIM + lc) = ob;
                    *(float2*)(Ksm + rla * PKF + lc) = oa;
                    *(float2*)(Ksm + rlb * PKF + lc) = ob;
                }
            }
        }
    }
    __syncthreads();

    // -------- fused G: G[a][d] = sum_j gamma^(64-j) K[j][a] V[j][d] ----------
    {
        const int a0 = (t >> 4) * 4;
        const int d0 = (t & 15) * 4;
        float acc[4][4];
        #pragma unroll
        for (int p = 0; p < 4; p++)
            #pragma unroll
            for (int q = 0; q < 4; q++) acc[p][q] = 0.f;

        for (int j = 0; j < CHUNK; j++) {
            float wj = wsm[j];
            float4 kq = *(const float4*)(Ksm + j * PKF + a0);
            float4 vq = *(const float4*)(Vsm + j * PKF + d0);
            float ka[4] = { kq.x * wj, kq.y * wj, kq.z * wj, kq.w * wj };
            float vd[4] = { vq.x, vq.y, vq.z, vq.w };
            #pragma unroll
            for (int p = 0; p < 4; p++)
                #pragma unroll
                for (int q = 0; q < 4; q++)
                    acc[p][q] = fmaf(ka[p], vd[q], acc[p][q]);
        }

        int gbase = blockIdx.x * DIM * DIM;    // blockIdx == global chunk index
        #pragma unroll
        for (int p = 0; p < 4; p++)
            *(float4*)(g_G + gbase + (a0 + p) * DIM + d0) =
                make_float4(acc[p][0], acc[p][1], acc[p][2], acc[p][3]);
    }
}

// ==== K3: elementwise scan, MLP=32 x 2 groups (fits registers, no spill) =====
__global__ __launch_bounds__(128) void scan_kernel() {
    int e = blockIdx.x * 128 + threadIdx.x;          // 0..8191
    int b  = e >> 12;
    int ed = e & (DIM * DIM - 1);
    const float g64 = powf(GAMMA_F, 64.0f);
    int base = b * NCHUNK * DIM * DIM + ed;
    const float* Gp = g_G + base;
    float*       Ap = g_A + base;
    float acc = 0.f;
    #pragma unroll
    for (int grp = 0; grp < 2; grp++) {
        float buf[32];
        #pragma unroll
        for (int u = 0; u < 32; u++)                 // 32 independent LDGs
            buf[u] = Gp[(grp * 32 + u) * (DIM * DIM)];
        #pragma unroll
        for (int u = 0; u < 32; u++) {
            Ap[(grp * 32 + u) * (DIM * DIM)] = acc;  // state BEFORE chunk
            acc = acc * g64 + buf[u];
        }
    }
}

// == K4: out = (Q K^T .* decay) V + diag(g^i)(Q A_c)
//    512 threads, 2x2 micro-tile, 2 blocks/chunk; compile-time causal skip.
#define PQ 34   // Qt/St pitch (floats): float2-aligned, conflict-free
#define PK 68   // Kt/Vt pitch (floats): float2/float4-aligned, conflict-free

template<int JMAX>
__device__ __forceinline__ void out_body(
    float* __restrict__ out, float* Qt, float* Kt, float* St,
    int base, int rbase, int cidx, int half)
{
    const int t = threadIdx.x;

    // Qt[a][i] = Q[rbase + i*64 + a]; Kt[a][j] = K[base + j*64 + a] (j < JMAX)
    #pragma unroll
    for (int q = 0; q < 4; q++) {
        int f = t + 512 * q;                 // i = f>>6, a = f&63
        Qt[(f & 63) * PQ + (f >> 6)] = g_Q[rbase + f];
    }
    #pragma unroll
    for (int q = 0; q < JMAX / 8; q++) {
        int f = t + 512 * q;                 // j = f>>6, a = f&63
        Kt[(f & 63) * PK + (f >> 6)] = g_K[base + f];
    }
    __syncthreads();

    const int ti = t >> 5, tj = t & 31;      // 16 x 32 thread grid
    const int i0 = ti * 2, j0 = tj * 2;

    // ---- phase 1: S = (Q K^T) .* gamma^(gi-j) causal mask (j < JMAX)
    if (JMAX == CHUNK || j0 < JMAX) {
        float s[2][2];
        s[0][0] = s[0][1] = s[1][0] = s[1][1] = 0.f;

        #pragma unroll 4
        for (int a = 0; a < DIM; a++) {
            float2 qa = *(const float2*)(Qt + a * PQ + i0);
            float2 kb = *(const float2*)(Kt + a * PK + j0);
            s[0][0] = fmaf(qa.x, kb.x, s[0][0]);
            s[0][1] = fmaf(qa.x, kb.y, s[0][1]);
            s[1][0] = fmaf(qa.y, kb.x, s[1][0]);
            s[1][1] = fmaf(qa.y, kb.y, s[1][1]);
        }
        #pragma unroll
        for (int p = 0; p < 2; p++) {
            int gi = half * 32 + i0 + p;
            #pragma unroll
            for (int q = 0; q < 2; q++) {
                int j = j0 + q;
                float v = (gi >= j) ? s[p][q] * exp2f(LG2G * (float)(gi - j)) : 0.f;
                St[j * PQ + (i0 + p)] = v;
            }
        }
    }
    __syncthreads();

    // overwrite Kt with V in [j][d] layout (j < JMAX)
    #pragma unroll
    for (int q = 0; q < JMAX / 8; q++) {
        int f = t + 512 * q;                 // j = f>>6, d = f&63
        Kt[(f >> 6) * PK + (f & 63)] = g_V[base + f];
    }
    __syncthreads();

    // ---- phase 2: out = S V + diag * (Q A)
    const int d0 = tj * 2;
    float o[2][2];
    o[0][0] = o[0][1] = o[1][0] = o[1][1] = 0.f;

    #pragma unroll 4
    for (int j = 0; j < JMAX; j++) {
        float2 sp = *(const float2*)(St + j * PQ + i0);
        float2 vv = *(const float2*)(Kt + j * PK + d0);
        o[0][0] = fmaf(sp.x, vv.x, o[0][0]);
        o[0][1] = fmaf(sp.x, vv.y, o[0][1]);
        o[1][0] = fmaf(sp.y, vv.x, o[1][0]);
        o[1][1] = fmaf(sp.y, vv.y, o[1][1]);
    }

    const float* A = g_A + cidx * DIM * DIM;
    float oa[2][2];
    oa[0][0] = oa[0][1] = oa[1][0] = oa[1][1] = 0.f;

    #pragma unroll 4
    for (int a = 0; a < DIM; a++) {
        float2 av = *(const float2*)(A + a * DIM + d0);
        float2 qa = *(const float2*)(Qt + a * PQ + i0);
        oa[0][0] = fmaf(qa.x, av.x, oa[0][0]);
        oa[0][1] = fmaf(qa.x, av.y, oa[0][1]);
        oa[1][0] = fmaf(qa.y, av.x, oa[1][0]);
        oa[1][1] = fmaf(qa.y, av.y, oa[1][1]);
    }

    #pragma unroll
    for (int p = 0; p < 2; p++) {
        int gi = half * 32 + i0 + p;
        float dec = exp2f(LG2G * (float)gi);
        float2 res;
        res.x = o[p][0] + dec * oa[p][0];
        res.y = o[p][1] + dec * oa[p][1];
        *(float2*)(out + rbase + (i0 + p) * 64 + d0) = res;
    }
}

__global__ __launch_bounds__(512) void out_kernel(float* __restrict__ out) {
    __shared__ float Qt[64 * PQ];   // [a][i]  a=0..63, i=0..31
    __shared__ float Kt[64 * PK];   // [a][j], reused as V [j][d] in phase 2
    __shared__ float St[64 * PQ];   // [j][i]

    const int idx  = blockIdx.x;
    const int half = idx & 1;
    const int cidx = idx >> 1;              // global chunk index 0..127
    const int base  = cidx * CHUNK * DIM;
    const int rbase = base + half * 32 * DIM;

    if (half)
        out_body<CHUNK>(out, Qt, Kt, St, base, rbase, cidx, half);
    else
        out_body<32>(out, Qt, Kt, St, base, rbase, cidx, half);
}

// ============================== launch ======================================
extern "C" void kernel_launch(void* const* d_in, const int* in_sizes, int n_in,
                              void* d_out, int out_size)
{
    const float* X  = (const float*)d_in[0];
    const float* WQ = (const float*)d_in[1];
    const float* WK = (const float*)d_in[2];
    const float* WV = (const float*)d_in[3];
    float* out = (float*)d_out;

    cudaFuncSetAttribute(gemm_kernel,
                         cudaFuncAttributeMaxDynamicSharedMemorySize, GEMM_SMEM);

    prep_kernel<<<512 + NTOT, 256>>>(WQ, WK, WV);
    gemm_kernel<<<NROWS / 64, 256, GEMM_SMEM>>>(X);
    scan_kernel<<<(BATCH * DIM * DIM) / 128, 128>>>();
    out_kernel<<<BATCH * NCHUNK * 2, 512>>>(out);
}